// round 6
// baseline (speedup 1.0000x reference)
#include <cuda_runtime.h>
#include <stdint.h>

// Problem constants (from reference): C=1, RC=1, P=12, Q=6
#define GAMMA 0.1f
#define MIN_R 0.1f
#define MAX_NODES 100000

// Padded fp32 accumulator [N,4] so each edge does ONE red.global.add.v4.f32
// (16B aligned) instead of three scalar atomics. __device__ global scratch:
// allocation-free, allowed by the harness rules.
__device__ __align__(16) float g_acc[MAX_NODES * 4];

__global__ void zero_acc_kernel(int n_nodes) {
    int i = blockIdx.x * blockDim.x + threadIdx.x;
    if (i < n_nodes) {
        reinterpret_cast<float4*>(g_acc)[i] = make_float4(0.f, 0.f, 0.f, 0.f);
    }
}

__global__ void edge_kernel(const float* __restrict__ x,
                            const int* __restrict__ src,
                            const int* __restrict__ dst,
                            int n_edges) {
    int e = blockIdx.x * blockDim.x + threadIdx.x;
    if (e >= n_edges) return;

    int s = src[e];   // coalesced 4B streaming loads (JAX int64 -> int32 downcast)
    int d = dst[e];

    // Random gathers — x (1.2MB) is L2-resident; issue all 6 loads up front for MLP.
    float sx = __ldg(x + 3 * s);
    float sy = __ldg(x + 3 * s + 1);
    float sz = __ldg(x + 3 * s + 2);
    float dx = __ldg(x + 3 * d);
    float dy = __ldg(x + 3 * d + 1);
    float dz = __ldg(x + 3 * d + 2);

    float drx = dx - sx;
    float dry = dy - sy;
    float drz = dz - sz;

    float r2 = drx * drx + dry * dry + drz * drz;
    float r  = sqrtf(r2);

    // lj_force with r clamped at MIN_R (RC=1, P=12, Q=6, C=1):
    //   f = 4 * s^6 * (12*s^6 - 6) / rc = s6*(48*s6 - 24) * s1
    float rc = fmaxf(r, MIN_R);
    float s1 = 1.0f / rc;
    float sq = s1 * s1;
    float s6 = sq * sq * sq;
    float f  = s6 * (48.0f * s6 - 24.0f) * s1;

    // msg = f * dr / max(||dr||, 1e-12)  (self-edges: dr=0 -> msg=0)
    float coeff = f / fmaxf(r, 1e-12f);

    float mx = coeff * drx;
    float my = coeff * dry;
    float mz = coeff * drz;

    float* p = g_acc + 4 * (size_t)d;   // 16B-aligned (stride 16B, base aligned)
    asm volatile("red.global.add.v4.f32 [%0], {%1, %2, %3, %4};"
                 :: "l"(p), "f"(mx), "f"(my), "f"(mz), "f"(0.0f)
                 : "memory");
}

__global__ void finish_kernel(const float* __restrict__ v,
                              float* __restrict__ out,
                              int n_nodes) {
    int i = blockIdx.x * blockDim.x + threadIdx.x;
    if (i < n_nodes) {
        float4 a = reinterpret_cast<const float4*>(g_acc)[i];
        out[3 * i]     = a.x - GAMMA * v[3 * i];
        out[3 * i + 1] = a.y - GAMMA * v[3 * i + 1];
        out[3 * i + 2] = a.z - GAMMA * v[3 * i + 2];
    }
}

extern "C" void kernel_launch(void* const* d_in, const int* in_sizes, int n_in,
                              void* d_out, int out_size) {
    // metadata order: x [N,3] f32, v [N,3] f32, src [E] i32, dst [E] i32, n_nodes
    const float* x   = (const float*)d_in[0];
    const float* v   = (const float*)d_in[1];
    const int*   src = (const int*)d_in[2];
    const int*   dst = (const int*)d_in[3];
    float* out = (float*)d_out;

    int n_nodes = in_sizes[0] / 3;
    int n_edges = in_sizes[2];

    const int T = 256;
    zero_acc_kernel<<<(n_nodes + T - 1) / T, T>>>(n_nodes);
    edge_kernel<<<(n_edges + T - 1) / T, T>>>(x, src, dst, n_edges);
    finish_kernel<<<(n_nodes + T - 1) / T, T>>>(v, out, n_nodes);
}

// round 11
// speedup vs baseline: 1.2287x; 1.2287x over previous
#include <cuda_runtime.h>
#include <stdint.h>

// Problem constants (from reference): C=1, RC=1, P=12, Q=6
#define GAMMA 0.1f
#define MIN_R 0.1f
#define MAX_NODES 100000

// Padded accumulator [N,4]: one red.global.add.v4.f32 per edge (16B aligned).
// INVARIANT: g_acc is all-zero on entry to every kernel_launch call.
// (Zero-initialized at module load; finish_kernel re-zeroes it each launch.)
__device__ __align__(16) float g_acc[MAX_NODES * 4];

// Padded positions [N,4] so each endpoint gather is a single LDG.128 hitting
// exactly one 32B L2 sector (vs 3 scalar loads over an unaligned 12B row).
__device__ __align__(16) float g_x4[MAX_NODES * 4];

__global__ void prep_kernel(const float* __restrict__ x, int n_nodes) {
    int i = blockIdx.x * blockDim.x + threadIdx.x;
    if (i < n_nodes) {
        float4 p;
        p.x = x[3 * i];
        p.y = x[3 * i + 1];
        p.z = x[3 * i + 2];
        p.w = 0.0f;
        reinterpret_cast<float4*>(g_x4)[i] = p;
    }
}

__global__ void edge_kernel(const int* __restrict__ src,
                            const int* __restrict__ dst,
                            int n_edges) {
    int e = blockIdx.x * blockDim.x + threadIdx.x;
    if (e >= n_edges) return;

    int s = src[e];   // coalesced 4B streaming loads
    int d = dst[e];

    // Two independent 16B gathers — 1 L2 sector each, L2-resident (1.6MB table).
    float4 xs = __ldg(reinterpret_cast<const float4*>(g_x4) + s);
    float4 xd = __ldg(reinterpret_cast<const float4*>(g_x4) + d);

    float drx = xd.x - xs.x;
    float dry = xd.y - xs.y;
    float drz = xd.z - xs.z;

    float r2 = drx * drx + dry * dry + drz * drz;
    float r  = sqrtf(r2);

    // lj_force with r clamped at MIN_R (RC=1, P=12, Q=6, C=1):
    //   f = s6*(48*s6 - 24) * s1,  s1 = 1/max(r, MIN_R)
    float rc = fmaxf(r, MIN_R);
    float s1 = 1.0f / rc;
    float sq = s1 * s1;
    float s6 = sq * sq * sq;
    float f  = s6 * (48.0f * s6 - 24.0f) * s1;

    // msg = f * dr / max(||dr||, 1e-12)  (self-edges: dr=0 -> msg=0)
    float coeff = f / fmaxf(r, 1e-12f);

    float mx = coeff * drx;
    float my = coeff * dry;
    float mz = coeff * drz;

    float* p = g_acc + 4 * (size_t)d;   // 16B-aligned
    asm volatile("red.global.add.v4.f32 [%0], {%1, %2, %3, %4};"
                 :: "l"(p), "f"(mx), "f"(my), "f"(mz), "f"(0.0f)
                 : "memory");
}

__global__ void finish_kernel(const float* __restrict__ v,
                              float* __restrict__ out,
                              int n_nodes) {
    int i = blockIdx.x * blockDim.x + threadIdx.x;
    if (i < n_nodes) {
        float4 a = reinterpret_cast<const float4*>(g_acc)[i];
        out[3 * i]     = a.x - GAMMA * v[3 * i];
        out[3 * i + 1] = a.y - GAMMA * v[3 * i + 1];
        out[3 * i + 2] = a.z - GAMMA * v[3 * i + 2];
        // Restore the all-zero invariant for the next launch (replaces the
        // dedicated zeroing kernel — saves one full launch).
        reinterpret_cast<float4*>(g_acc)[i] = make_float4(0.f, 0.f, 0.f, 0.f);
    }
}

extern "C" void kernel_launch(void* const* d_in, const int* in_sizes, int n_in,
                              void* d_out, int out_size) {
    // metadata order: x [N,3] f32, v [N,3] f32, src [E] i32, dst [E] i32, n_nodes
    const float* x   = (const float*)d_in[0];
    const float* v   = (const float*)d_in[1];
    const int*   src = (const int*)d_in[2];
    const int*   dst = (const int*)d_in[3];
    float* out = (float*)d_out;

    int n_nodes = in_sizes[0] / 3;
    int n_edges = in_sizes[2];

    const int T = 256;
    prep_kernel<<<(n_nodes + T - 1) / T, T>>>(x, n_nodes);
    edge_kernel<<<(n_edges + T - 1) / T, T>>>(src, dst, n_edges);
    finish_kernel<<<(n_nodes + T - 1) / T, T>>>(v, out, n_nodes);
}